// round 10
// baseline (speedup 1.0000x reference)
#include <cuda_runtime.h>
#include <cstdint>

#define NN 100000      // nodes
#define EE 1600000     // edges
#define PP 100000      // pairs (each of pos/neg)
#define DH 128
#define DMLP 512
#define DPRED 64
#define LAYERS 3
#define SCAN_B 1024
#define SCAN_NB ((NN + SCAN_B - 1) / SCAN_B)   // 98

// ---------------- scratch (static device allocations) ----------------
__device__ float  g_h[(size_t)NN * DH];                  // fp32 h between layers
__device__ float  g_z[(size_t)NN * DMLP];                // fp32 z (GEMM1 out)
__device__ int8_t g_zq1[(size_t)NN * DMLP], g_zq2[(size_t)NN * DMLP];
__device__ float  g_sz[NN];
__device__ int8_t g_aq1[(size_t)NN * DH], g_aq2[(size_t)NN * DH];
__device__ float  g_sa[NN];
__device__ int8_t g_w1q1[LAYERS * DMLP * DH], g_w1q2[LAYERS * DMLP * DH];
__device__ float  g_sw1[LAYERS * DMLP];
__device__ int8_t g_w2q1[LAYERS * DH * DMLP], g_w2q2[LAYERS * DH * DMLP];
__device__ float  g_sw2[LAYERS * DH];
__device__ int8_t g_wpq1[DPRED * DH], g_wpq2[DPRED * DH];
__device__ float  g_swp[DPRED];
__device__ int8_t g_vq1[(size_t)2 * PP * DH], g_vq2[(size_t)2 * PP * DH];
__device__ float  g_sv[2 * PP];
__device__ float  g_wt[LAYERS * DMLP * DH];              // fp32 transpose temp
// CSR scratch
__device__ int g_deg[NN], g_incl[NN], g_off[NN], g_cur[NN], g_bsum[128], g_csr[EE];

static inline int cdiv(int a, int b) { return (a + b - 1) / b; }

// ---------------- common helpers ----------------
__device__ __forceinline__ uint32_t swz64(uint32_t off) { return off ^ ((off >> 3) & 0x30u); }

__device__ __forceinline__ void cpasync16(uint32_t dst, const void* src, bool pred) {
    asm volatile("cp.async.cg.shared.global [%0], [%1], 16, %2;"
                 :: "r"(dst), "l"(src), "r"(pred ? 16 : 0) : "memory");
}
__device__ __forceinline__ void cp_commit() {
    asm volatile("cp.async.commit_group;" ::: "memory");
}
template<int N> __device__ __forceinline__ void cp_wait() {
    asm volatile("cp.async.wait_group %0;" :: "n"(N) : "memory");
}
__device__ __forceinline__ void mma_s8(int* c, const uint32_t* a, const uint32_t* b) {
    asm volatile("mma.sync.aligned.m16n8k32.row.col.s32.s8.s8.s32 "
                 "{%0,%1,%2,%3}, {%4,%5,%6,%7}, {%8,%9}, {%0,%1,%2,%3};"
                 : "+r"(c[0]), "+r"(c[1]), "+r"(c[2]), "+r"(c[3])
                 : "r"(a[0]), "r"(a[1]), "r"(a[2]), "r"(a[3]), "r"(b[0]), "r"(b[1]));
}
__device__ __forceinline__ void ldsm4(uint32_t addr, uint32_t* r) {
    asm volatile("ldmatrix.sync.aligned.m8n8.x4.shared.b16 {%0,%1,%2,%3}, [%4];"
                 : "=r"(r[0]), "=r"(r[1]), "=r"(r[2]), "=r"(r[3]) : "r"(addr));
}

// quantize 4 floats with inverse scale si: q1 word + q2 word
__device__ __forceinline__ void quant4(float4 v, float si, uint32_t& w1, uint32_t& w2) {
    int a0 = __float2int_rn(v.x * si), a1 = __float2int_rn(v.y * si);
    int a2 = __float2int_rn(v.z * si), a3 = __float2int_rn(v.w * si);
    int b0 = __float2int_rn((v.x * si - (float)a0) * 254.f);
    int b1 = __float2int_rn((v.y * si - (float)a1) * 254.f);
    int b2 = __float2int_rn((v.z * si - (float)a2) * 254.f);
    int b3 = __float2int_rn((v.w * si - (float)a3) * 254.f);
    w1 = (a0 & 0xff) | ((a1 & 0xff) << 8) | ((a2 & 0xff) << 16) | ((a3 & 0xff) << 24);
    w2 = (b0 & 0xff) | ((b1 & 0xff) << 8) | ((b2 & 0xff) << 16) | ((b3 & 0xff) << 24);
}

// ---------------- CSR build kernels ----------------
__global__ void zero_int_kernel(int* __restrict__ p, int n) {
    int i = blockIdx.x * blockDim.x + threadIdx.x;
    if (i < n) p[i] = 0;
}
__global__ void hist_kernel(const int* __restrict__ dst, int* __restrict__ deg, int E) {
    int e = blockIdx.x * blockDim.x + threadIdx.x;
    if (e < E) atomicAdd(&deg[__ldg(dst + e)], 1);
}
__global__ void scan_block_kernel(const int* __restrict__ deg, int* __restrict__ incl,
                                  int* __restrict__ bsum, int n) {
    __shared__ int sm[SCAN_B];
    int i = blockIdx.x * SCAN_B + threadIdx.x;
    int v = (i < n) ? deg[i] : 0;
    sm[threadIdx.x] = v;
    __syncthreads();
    for (int o = 1; o < SCAN_B; o <<= 1) {
        int t = (threadIdx.x >= o) ? sm[threadIdx.x - o] : 0;
        __syncthreads();
        sm[threadIdx.x] += t;
        __syncthreads();
    }
    if (i < n) incl[i] = sm[threadIdx.x];
    if (threadIdx.x == SCAN_B - 1) bsum[blockIdx.x] = sm[SCAN_B - 1];
}
__global__ void scan_sums_kernel(int* __restrict__ bsum, int nb) {
    __shared__ int sm[128];
    int v = (threadIdx.x < nb) ? bsum[threadIdx.x] : 0;
    sm[threadIdx.x] = v;
    __syncthreads();
    for (int o = 1; o < 128; o <<= 1) {
        int t = (threadIdx.x >= o) ? sm[threadIdx.x - o] : 0;
        __syncthreads();
        sm[threadIdx.x] += t;
        __syncthreads();
    }
    if (threadIdx.x < nb) bsum[threadIdx.x] = sm[threadIdx.x] - v;
}
__global__ void finalize_off_kernel(const int* __restrict__ incl, const int* __restrict__ deg,
                                    const int* __restrict__ bsum,
                                    int* __restrict__ off, int* __restrict__ cur, int n) {
    int i = blockIdx.x * blockDim.x + threadIdx.x;
    if (i >= n) return;
    int o = incl[i] - deg[i] + bsum[i / SCAN_B];
    off[i] = o;
    cur[i] = o;
}
__global__ void fill_kernel(const int* __restrict__ src, const int* __restrict__ dst,
                            int* __restrict__ cur, int* __restrict__ csr, int E) {
    int e = blockIdx.x * blockDim.x + threadIdx.x;
    if (e >= E) return;
    int p = atomicAdd(&cur[__ldg(dst + e)], 1);
    csr[p] = __ldg(src + e);
}

// ---------------- gather + self + int8 row-quant (warp per node, K=128) ----------------
__global__ void gather_quant_kernel(const float* __restrict__ h,
                                    const int* __restrict__ off, const int* __restrict__ deg,
                                    const int* __restrict__ csr,
                                    int8_t* __restrict__ q1, int8_t* __restrict__ q2,
                                    float* __restrict__ scale, int n) {
    int widx = (blockIdx.x * blockDim.x + threadIdx.x) >> 5;
    if (widx >= n) return;
    int lane = threadIdx.x & 31;
    int c = lane << 2;
    float4 acc = *(const float4*)(h + (size_t)widx * DH + c);
    int s = __ldg(off + widx);
    int e = s + __ldg(deg + widx);
    int j = s;
    for (; j + 4 <= e; j += 4) {
        int i0 = __ldg(csr + j), i1 = __ldg(csr + j + 1);
        int i2 = __ldg(csr + j + 2), i3 = __ldg(csr + j + 3);
        float4 v0 = *(const float4*)(h + (size_t)i0 * DH + c);
        float4 v1 = *(const float4*)(h + (size_t)i1 * DH + c);
        float4 v2 = *(const float4*)(h + (size_t)i2 * DH + c);
        float4 v3 = *(const float4*)(h + (size_t)i3 * DH + c);
        acc.x += v0.x + v1.x + v2.x + v3.x;
        acc.y += v0.y + v1.y + v2.y + v3.y;
        acc.z += v0.z + v1.z + v2.z + v3.z;
        acc.w += v0.w + v1.w + v2.w + v3.w;
    }
    for (; j < e; j++) {
        int i0 = __ldg(csr + j);
        float4 v0 = *(const float4*)(h + (size_t)i0 * DH + c);
        acc.x += v0.x; acc.y += v0.y; acc.z += v0.z; acc.w += v0.w;
    }
    float m = fmaxf(fmaxf(fabsf(acc.x), fabsf(acc.y)), fmaxf(fabsf(acc.z), fabsf(acc.w)));
#pragma unroll
    for (int o = 16; o > 0; o >>= 1) m = fmaxf(m, __shfl_xor_sync(0xffffffffu, m, o));
    float si = (m > 1e-30f) ? 127.f / m : 0.f;
    if (lane == 0) scale[widx] = m * (1.f / 127.f);
    uint32_t w1, w2;
    quant4(acc, si, w1, w2);
    ((uint32_t*)q1)[(size_t)widx * 32 + lane] = w1;
    ((uint32_t*)q2)[(size_t)widx * 32 + lane] = w2;
}

// ---------------- generic fp32 row quantizer (warp per row; K in {128,512}) ----------------
__global__ void rowquant_kernel(const float* __restrict__ in,
                                int8_t* __restrict__ q1, int8_t* __restrict__ q2,
                                float* __restrict__ scale, int rows, int K) {
    int row = (blockIdx.x * blockDim.x + threadIdx.x) >> 5;
    if (row >= rows) return;
    int lane = threadIdx.x & 31;
    const float* rp = in + (size_t)row * K;
    int nj = K >> 7;
    float4 v[4];
    float m = 0.f;
    for (int j = 0; j < nj; j++) {
        v[j] = *(const float4*)(rp + lane * 4 + j * 128);
        m = fmaxf(m, fmaxf(fmaxf(fabsf(v[j].x), fabsf(v[j].y)),
                           fmaxf(fabsf(v[j].z), fabsf(v[j].w))));
    }
#pragma unroll
    for (int o = 16; o > 0; o >>= 1) m = fmaxf(m, __shfl_xor_sync(0xffffffffu, m, o));
    float si = (m > 1e-30f) ? 127.f / m : 0.f;
    if (lane == 0) scale[row] = m * (1.f / 127.f);
    for (int j = 0; j < nj; j++) {
        uint32_t w1, w2;
        quant4(v[j], si, w1, w2);
        size_t wi = (size_t)row * (K >> 2) + lane + j * 32;
        ((uint32_t*)q1)[wi] = w1;
        ((uint32_t*)q2)[wi] = w2;
    }
}

// in[b][R][C] fp32 -> out[b][C][R] fp32; R,C multiples of 32
__global__ void transpose_kernel(const float* __restrict__ in, float* __restrict__ out,
                                 int R, int C) {
    __shared__ float tile[32][33];
    const float* ib = in + (size_t)blockIdx.z * R * C;
    float* ob = out + (size_t)blockIdx.z * R * C;
    int r = blockIdx.y * 32 + threadIdx.y;
    int c = blockIdx.x * 32 + threadIdx.x;
    tile[threadIdx.y][threadIdx.x] = ib[(size_t)r * C + c];
    __syncthreads();
    int ro = blockIdx.x * 32 + threadIdx.y;
    int co = blockIdx.y * 32 + threadIdx.x;
    ob[(size_t)ro * R + co] = tile[threadIdx.x][threadIdx.y];
}

// ---------------- predictor: V = h[src]*h[dst], row-quantized ----------------
__global__ void build_v_quant_kernel(const float* __restrict__ h,
                                     const int* __restrict__ psrc, const int* __restrict__ pdst,
                                     const int* __restrict__ nsrc, const int* __restrict__ ndst,
                                     int8_t* __restrict__ q1, int8_t* __restrict__ q2,
                                     float* __restrict__ scale, int P) {
    int p = (blockIdx.x * blockDim.x + threadIdx.x) >> 5;
    if (p >= 2 * P) return;
    int lane = threadIdx.x & 31;
    int c = lane << 2;
    int s, d;
    if (p < P) { s = __ldg(psrc + p); d = __ldg(pdst + p); }
    else       { s = __ldg(nsrc + p - P); d = __ldg(ndst + p - P); }
    float4 a = *(const float4*)(h + (size_t)s * DH + c);
    float4 b = *(const float4*)(h + (size_t)d * DH + c);
    float4 v = make_float4(a.x * b.x, a.y * b.y, a.z * b.z, a.w * b.w);
    float m = fmaxf(fmaxf(fabsf(v.x), fabsf(v.y)), fmaxf(fabsf(v.z), fabsf(v.w)));
#pragma unroll
    for (int o = 16; o > 0; o >>= 1) m = fmaxf(m, __shfl_xor_sync(0xffffffffu, m, o));
    float si = (m > 1e-30f) ? 127.f / m : 0.f;
    if (lane == 0) scale[p] = m * (1.f / 127.f);
    uint32_t w1, w2;
    quant4(v, si, w1, w2);
    ((uint32_t*)q1)[(size_t)p * 32 + lane] = w1;
    ((uint32_t*)q2)[(size_t)p * 32 + lane] = w2;
}

// ================= int8 2-digit tensor-core GEMM =================
// C[M,N] = relu( sa[r]*sb[c]*(P1 + P2/254) + bias[c] ), P1 = q1a.q1b, P2 = q1a.q2b + q2a.q1b
// A terms [M,K] int8 row-major; B terms [N,K] int8 row-major. BK=64 elems (64B rows, swz64).
template<int BM, int BN, int WM, int WN, int STAGES>
__global__ void __launch_bounds__((BM / WM) * (BN / WN) * 32)
i8_gemm(const int8_t* __restrict__ A1, const int8_t* __restrict__ A2,
        const float* __restrict__ sa,
        const int8_t* __restrict__ B1, const int8_t* __restrict__ B2,
        const float* __restrict__ sb, const float* __restrict__ bias,
        float* __restrict__ C, int M, int N, int K) {
    constexpr int THREADS = (BM / WM) * (BN / WN) * 32;
    constexpr int BK = 64;                 // int8 elements per chunk
    constexpr int ATB = BM * BK;           // bytes per A tile term
    constexpr int BTB = BN * BK;
    constexpr int STAGE = 2 * ATB + 2 * BTB;
    constexpr int AG = BM * 4;             // 16B granules per A term
    constexpr int BG = BN * 4;
    constexpr int MF = WM / 16;
    constexpr int NF = WN / 8;

    extern __shared__ char smem[];
    const uint32_t sbase = (uint32_t)__cvta_generic_to_shared(smem);

    const int tid = threadIdx.x;
    const int lane = tid & 31;
    const int w = tid >> 5;
    constexpr int WN_CNT = BN / WN;
    const int wn = w % WN_CNT;
    const int wm = w / WN_CNT;
    const int row0 = blockIdx.x * BM;
    const int col0 = blockIdx.y * BN;
    const int T = K / BK;

    int acc1[MF][NF][4], acc2[MF][NF][4];
#pragma unroll
    for (int i = 0; i < MF; i++)
#pragma unroll
        for (int j = 0; j < NF; j++)
#pragma unroll
            for (int q = 0; q < 4; q++) { acc1[i][j][q] = 0; acc2[i][j][q] = 0; }

    auto load_stage = [&](int s, int t) {
        const uint32_t st = sbase + s * STAGE;
        const int k0 = t * BK;
#pragma unroll
        for (int gid = tid; gid < AG; gid += THREADS) {
            int r = gid >> 2, g = gid & 3;
            bool p = (row0 + r) < M;
            size_t off = (size_t)(row0 + r) * K + k0 + g * 16;
            uint32_t d = st + swz64((uint32_t)(r * 64 + g * 16));
            cpasync16(d, A1 + off, p);
            cpasync16(d + ATB, A2 + off, p);
        }
#pragma unroll
        for (int gid = tid; gid < BG; gid += THREADS) {
            int r = gid >> 2, g = gid & 3;
            size_t off = (size_t)(col0 + r) * K + k0 + g * 16;
            uint32_t d = st + 2 * ATB + swz64((uint32_t)(r * 64 + g * 16));
            cpasync16(d, B1 + off, true);
            cpasync16(d + BTB, B2 + off, true);
        }
    };

#pragma unroll
    for (int s = 0; s < STAGES - 1; s++) {
        if (s < T) load_stage(s, s);
        cp_commit();
    }

    const int lrow = lane & 15;
    const int lcolb = ((lane >> 4) & 1) * 16;

    for (int t = 0; t < T; ++t) {
        cp_wait<STAGES - 2>();
        __syncthreads();
        if (t + STAGES - 1 < T) load_stage((t + STAGES - 1) % STAGES, t + STAGES - 1);
        cp_commit();

        const uint32_t st = sbase + (t % STAGES) * STAGE;
        const uint32_t bA1 = st, bA2 = st + ATB;
        const uint32_t bB1 = st + 2 * ATB, bB2 = bB1 + BTB;
#pragma unroll
        for (int ks = 0; ks < 2; ks++) {       // two k32 steps per 64B row
            uint32_t a1[MF][4], a2[MF][4];
            uint32_t b1[NF][2], b2[NF][2];
#pragma unroll
            for (int mf = 0; mf < MF; mf++) {
                uint32_t off = swz64((uint32_t)(wm * WM + mf * 16 + lrow) * 64
                                     + ks * 32 + lcolb);
                ldsm4(bA1 + off, a1[mf]);
                ldsm4(bA2 + off, a2[mf]);
            }
#pragma unroll
            for (int nf2 = 0; nf2 < NF / 2; nf2++) {
                uint32_t off = swz64((uint32_t)(wn * WN + nf2 * 16 + lrow) * 64
                                     + ks * 32 + lcolb);
                uint32_t r4[4];
                ldsm4(bB1 + off, r4);
                b1[nf2 * 2 + 0][0] = r4[0]; b1[nf2 * 2 + 1][0] = r4[1];
                b1[nf2 * 2 + 0][1] = r4[2]; b1[nf2 * 2 + 1][1] = r4[3];
                ldsm4(bB2 + off, r4);
                b2[nf2 * 2 + 0][0] = r4[0]; b2[nf2 * 2 + 1][0] = r4[1];
                b2[nf2 * 2 + 0][1] = r4[2]; b2[nf2 * 2 + 1][1] = r4[3];
            }
#pragma unroll
            for (int mf = 0; mf < MF; mf++)
#pragma unroll
                for (int nf = 0; nf < NF; nf++) {
                    mma_s8(acc1[mf][nf], a1[mf], b1[nf]);
                    mma_s8(acc2[mf][nf], a1[mf], b2[nf]);
                    mma_s8(acc2[mf][nf], a2[mf], b1[nf]);
                }
        }
        __syncthreads();
    }

    // ---- epilogue: rescale + bias + relu ----
#pragma unroll
    for (int mf = 0; mf < MF; mf++) {
        int r = row0 + wm * WM + mf * 16 + (lane >> 2);
        float sa0 = (r < M) ? __ldg(sa + r) : 0.f;
        float sa1 = (r + 8 < M) ? __ldg(sa + r + 8) : 0.f;
#pragma unroll
        for (int nf = 0; nf < NF; nf++) {
            int c = col0 + wn * WN + nf * 8 + (lane & 3) * 2;
            float sb0 = __ldg(sb + c), sb1 = __ldg(sb + c + 1);
            float b0 = __ldg(bias + c), b1v = __ldg(bias + c + 1);
#pragma unroll
            for (int half = 0; half < 2; half++) {
                int rr = r + half * 8;
                if (rr >= M) continue;
                float sA = half ? sa1 : sa0;
                float p0 = (float)acc1[mf][nf][half * 2 + 0]
                         + (float)acc2[mf][nf][half * 2 + 0] * (1.f / 254.f);
                float p1 = (float)acc1[mf][nf][half * 2 + 1]
                         + (float)acc2[mf][nf][half * 2 + 1] * (1.f / 254.f);
                float v0 = fmaxf(sA * sb0 * p0 + b0, 0.f);
                float v1 = fmaxf(sA * sb1 * p1 + b1v, 0.f);
                *(float2*)(C + (size_t)rr * N + c) = make_float2(v0, v1);
            }
        }
    }
}

// ================= predictor int8 GEMM with fused matvec epilogue =================
// out[r] = relu( sv[r]*swp[c]*(P1+P2/254) + bp1[c] ) . Wp2 + bp2. BM=128, BN=64, K=128.
__global__ void __launch_bounds__(128)
pred_i8_gemm(const int8_t* __restrict__ A1, const int8_t* __restrict__ A2,
             const float* __restrict__ sa,
             const int8_t* __restrict__ B1, const int8_t* __restrict__ B2,
             const float* __restrict__ sb,
             const float* __restrict__ bp1, const float* __restrict__ Wp2,
             const float* __restrict__ bp2, float* __restrict__ out,
             int M, int K) {
    constexpr int BM = 128, BN = 64, WM = 64, WN = 32, STAGES = 3, BK = 64;
    constexpr int THREADS = 128;
    constexpr int ATB = BM * BK;
    constexpr int BTB = BN * BK;
    constexpr int STAGE = 2 * ATB + 2 * BTB;
    constexpr int AG = BM * 4;
    constexpr int BG = BN * 4;
    constexpr int MF = WM / 16;   // 4
    constexpr int NF = WN / 8;    // 4

    extern __shared__ char smem[];
    const uint32_t sbase = (uint32_t)__cvta_generic_to_shared(smem);
    float* sred = (float*)smem;

    const int tid = threadIdx.x;
    const int lane = tid & 31;
    const int w = tid >> 5;
    const int wn = w & 1;
    const int wm = w >> 1;
    const int row0 = blockIdx.x * BM;
    const int T = K / BK;

    int acc1[MF][NF][4], acc2[MF][NF][4];
#pragma unroll
    for (int i = 0; i < MF; i++)
#pragma unroll
        for (int j = 0; j < NF; j++)
#pragma unroll
            for (int q = 0; q < 4; q++) { acc1[i][j][q] = 0; acc2[i][j][q] = 0; }

    auto load_stage = [&](int s, int t) {
        const uint32_t st = sbase + s * STAGE;
        const int k0 = t * BK;
#pragma unroll
        for (int gid = tid; gid < AG; gid += THREADS) {
            int r = gid >> 2, g = gid & 3;
            bool p = (row0 + r) < M;
            size_t off = (size_t)(row0 + r) * K + k0 + g * 16;
            uint32_t d = st + swz64((uint32_t)(r * 64 + g * 16));
            cpasync16(d, A1 + off, p);
            cpasync16(d + ATB, A2 + off, p);
        }
#pragma unroll
        for (int gid = tid; gid < BG; gid += THREADS) {
            int r = gid >> 2, g = gid & 3;
            size_t off = (size_t)r * K + k0 + g * 16;
            uint32_t d = st + 2 * ATB + swz64((uint32_t)(r * 64 + g * 16));
            cpasync16(d, B1 + off, true);
            cpasync16(d + BTB, B2 + off, true);
        }
    };

#pragma unroll
    for (int s = 0; s < STAGES - 1; s++) {
        if (s < T) load_stage(s, s);
        cp_commit();
    }

    const int lrow = lane & 15;
    const int lcolb = ((lane >> 4) & 1) * 16;

    for (int t = 0; t < T; ++t) {
        cp_wait<STAGES - 2>();
        __syncthreads();
        if (t + STAGES - 1 < T) load_stage((t + STAGES - 1) % STAGES, t + STAGES - 1);
        cp_commit();

        const uint32_t st = sbase + (t % STAGES) * STAGE;
        const uint32_t bA1 = st, bA2 = st + ATB;
        const uint32_t bB1 = st + 2 * ATB, bB2 = bB1 + BTB;
#pragma unroll
        for (int ks = 0; ks < 2; ks++) {
            uint32_t a1[MF][4], a2[MF][4];
            uint32_t b1[NF][2], b2[NF][2];
#pragma unroll
            for (int mf = 0; mf < MF; mf++) {
                uint32_t off = swz64((uint32_t)(wm * WM + mf * 16 + lrow) * 64
                                     + ks * 32 + lcolb);
                ldsm4(bA1 + off, a1[mf]);
                ldsm4(bA2 + off, a2[mf]);
            }
#pragma unroll
            for (int nf2 = 0; nf2 < NF / 2; nf2++) {
                uint32_t off = swz64((uint32_t)(wn * WN + nf2 * 16 + lrow) * 64
                                     + ks * 32 + lcolb);
                uint32_t r4[4];
                ldsm4(bB1 + off, r4);
                b1[nf2 * 2 + 0][0] = r4[0]; b1[nf2 * 2 + 1][0] = r4[1];
                b1[nf2 * 2 + 0][1] = r4[2]; b1[nf2 * 2 + 1][1] = r4[3];
                ldsm4(bB2 + off, r4);
                b2[nf2 * 2 + 0][0] = r4[0]; b2[nf2 * 2 + 1][0] = r4[1];
                b2[nf2 * 2 + 0][1] = r4[2]; b2[nf2 * 2 + 1][1] = r4[3];
            }
#pragma unroll
            for (int mf = 0; mf < MF; mf++)
#pragma unroll
                for (int nf = 0; nf < NF; nf++) {
                    mma_s8(acc1[mf][nf], a1[mf], b1[nf]);
                    mma_s8(acc2[mf][nf], a1[mf], b2[nf]);
                    mma_s8(acc2[mf][nf], a2[mf], b1[nf]);
                }
        }
        __syncthreads();
    }

    // ---- fused epilogue ----
#pragma unroll
    for (int mf = 0; mf < MF; mf++) {
        int r = row0 + wm * WM + mf * 16 + (lane >> 2);
        float sa0 = (r < M) ? __ldg(sa + r) : 0.f;
        float sa1 = (r + 8 < M) ? __ldg(sa + r + 8) : 0.f;
        float part0 = 0.f, part1 = 0.f;
#pragma unroll
        for (int nf = 0; nf < NF; nf++) {
            int c = wn * WN + nf * 8 + (lane & 3) * 2;
            float sb0 = __ldg(sb + c), sb1 = __ldg(sb + c + 1);
            float b0 = __ldg(bp1 + c), b1v = __ldg(bp1 + c + 1);
            float w0 = __ldg(Wp2 + c), w1v = __ldg(Wp2 + c + 1);
            float p00 = (float)acc1[mf][nf][0] + (float)acc2[mf][nf][0] * (1.f / 254.f);
            float p01 = (float)acc1[mf][nf][1] + (float)acc2[mf][nf][1] * (1.f / 254.f);
            float p10 = (float)acc1[mf][nf][2] + (float)acc2[mf][nf][2] * (1.f / 254.f);
            float p11 = (float)acc1[mf][nf][3] + (float)acc2[mf][nf][3] * (1.f / 254.f);
            part0 += fmaxf(sa0 * sb0 * p00 + b0, 0.f) * w0
                   + fmaxf(sa0 * sb1 * p01 + b1v, 0.f) * w1v;
            part1 += fmaxf(sa1 * sb0 * p10 + b0, 0.f) * w0
                   + fmaxf(sa1 * sb1 * p11 + b1v, 0.f) * w1v;
        }
#pragma unroll
        for (int o = 1; o < 4; o <<= 1) {
            part0 += __shfl_xor_sync(0xffffffffu, part0, o);
            part1 += __shfl_xor_sync(0xffffffffu, part1, o);
        }
        if ((lane & 3) == 0) {
            int lr = wm * WM + mf * 16 + (lane >> 2);
            sred[wn * 128 + lr] = part0;
            sred[wn * 128 + lr + 8] = part1;
        }
    }
    __syncthreads();
    {
        int r = row0 + tid;
        if (r < M) out[r] = sred[tid] + sred[128 + tid] + __ldg(bp2);
    }
}

// ---------------- launch ----------------
extern "C" void kernel_launch(void* const* d_in, const int* in_sizes, int n_in,
                              void* d_out, int out_size) {
    const float* x    = (const float*)d_in[0];
    const float* W1   = (const float*)d_in[1];
    const float* b1   = (const float*)d_in[2];
    const float* W2   = (const float*)d_in[3];
    const float* b2   = (const float*)d_in[4];
    const float* Wp1  = (const float*)d_in[5];
    const float* bp1  = (const float*)d_in[6];
    const float* Wp2  = (const float*)d_in[7];
    const float* bp2  = (const float*)d_in[8];
    const int*   esrc = (const int*)d_in[9];
    const int*   edst = (const int*)d_in[10];
    const int*   psrc = (const int*)d_in[11];
    const int*   pdst = (const int*)d_in[12];
    const int*   nsrc = (const int*)d_in[13];
    const int*   ndst = (const int*)d_in[14];
    float* out = (float*)d_out;

    float *hbuf, *z, *sz, *saq, *sw1, *sw2, *swp, *sv, *wt;
    int8_t *zq1, *zq2, *aq1, *aq2, *w1q1, *w1q2, *w2q1, *w2q2, *wpq1, *wpq2, *vq1, *vq2;
    int *deg, *incl, *off, *cur, *bsum, *csr;
    cudaGetSymbolAddress((void**)&hbuf, g_h);
    cudaGetSymbolAddress((void**)&z,    g_z);
    cudaGetSymbolAddress((void**)&zq1,  g_zq1);
    cudaGetSymbolAddress((void**)&zq2,  g_zq2);
    cudaGetSymbolAddress((void**)&sz,   g_sz);
    cudaGetSymbolAddress((void**)&aq1,  g_aq1);
    cudaGetSymbolAddress((void**)&aq2,  g_aq2);
    cudaGetSymbolAddress((void**)&saq,  g_sa);
    cudaGetSymbolAddress((void**)&w1q1, g_w1q1);
    cudaGetSymbolAddress((void**)&w1q2, g_w1q2);
    cudaGetSymbolAddress((void**)&sw1,  g_sw1);
    cudaGetSymbolAddress((void**)&w2q1, g_w2q1);
    cudaGetSymbolAddress((void**)&w2q2, g_w2q2);
    cudaGetSymbolAddress((void**)&sw2,  g_sw2);
    cudaGetSymbolAddress((void**)&wpq1, g_wpq1);
    cudaGetSymbolAddress((void**)&wpq2, g_wpq2);
    cudaGetSymbolAddress((void**)&swp,  g_swp);
    cudaGetSymbolAddress((void**)&vq1,  g_vq1);
    cudaGetSymbolAddress((void**)&vq2,  g_vq2);
    cudaGetSymbolAddress((void**)&sv,   g_sv);
    cudaGetSymbolAddress((void**)&wt,   g_wt);
    cudaGetSymbolAddress((void**)&deg,  g_deg);
    cudaGetSymbolAddress((void**)&incl, g_incl);
    cudaGetSymbolAddress((void**)&off,  g_off);
    cudaGetSymbolAddress((void**)&cur,  g_cur);
    cudaGetSymbolAddress((void**)&bsum, g_bsum);
    cudaGetSymbolAddress((void**)&csr,  g_csr);

    // smem per stage: 2*(BM*64)+2*(BN*64); 3 stages
    constexpr int SMEM_MAIN = 3 * (2 * 128 * 64 + 2 * 128 * 64);   // 96 KB
    constexpr int SMEM_PRED = 3 * (2 * 128 * 64 + 2 * 64 * 64);    // 72 KB
    cudaFuncSetAttribute(i8_gemm<128, 128, 64, 32, 3>,
                         cudaFuncAttributeMaxDynamicSharedMemorySize, SMEM_MAIN);
    cudaFuncSetAttribute(pred_i8_gemm,
                         cudaFuncAttributeMaxDynamicSharedMemorySize, SMEM_PRED);

    float* out_h = out + 2 * PP;   // final h ([N,128]) lives in output

    // ---- CSR build ----
    zero_int_kernel<<<cdiv(NN, 256), 256>>>(deg, NN);
    hist_kernel<<<cdiv(EE, 256), 256>>>(edst, deg, EE);
    scan_block_kernel<<<SCAN_NB, SCAN_B>>>(deg, incl, bsum, NN);
    scan_sums_kernel<<<1, 128>>>(bsum, SCAN_NB);
    finalize_off_kernel<<<cdiv(NN, 256), 256>>>(incl, deg, bsum, off, cur, NN);
    fill_kernel<<<cdiv(EE, 256), 256>>>(esrc, edst, cur, csr, EE);

    // ---- weight transpose + row quant ----
    transpose_kernel<<<dim3(DMLP / 32, DH / 32, LAYERS), dim3(32, 32)>>>(W1, wt, DH, DMLP);
    rowquant_kernel<<<cdiv(LAYERS * DMLP * 32, 256), 256>>>(wt, w1q1, w1q2, sw1,
                                                            LAYERS * DMLP, DH);
    transpose_kernel<<<dim3(DH / 32, DMLP / 32, LAYERS), dim3(32, 32)>>>(W2, wt, DMLP, DH);
    rowquant_kernel<<<cdiv(LAYERS * DH * 32, 256), 256>>>(wt, w2q1, w2q2, sw2,
                                                          LAYERS * DH, DMLP);
    transpose_kernel<<<dim3(DPRED / 32, DH / 32, 1), dim3(32, 32)>>>(Wp1, wt, DH, DPRED);
    rowquant_kernel<<<cdiv(DPRED * 32, 256), 256>>>(wt, wpq1, wpq2, swp, DPRED, DH);

    const int M = NN;
    for (int l = 0; l < LAYERS; l++) {
        const float* hcur = (l == 0) ? x : hbuf;
        float* hnext = (l == LAYERS - 1) ? out_h : hbuf;

        // agg = h + sum_neighbors h, quantized int8 2-digit (fused)
        gather_quant_kernel<<<cdiv(NN * 32, 256), 256>>>(hcur, off, deg, csr,
                                                         aq1, aq2, saq, NN);
        // z = relu(agg @ W1 + b1)  [M,512] fp32
        i8_gemm<128, 128, 64, 32, 3>
            <<<dim3(cdiv(M, 128), DMLP / 128), 256, SMEM_MAIN>>>(
                aq1, aq2, saq,
                w1q1 + (size_t)l * DMLP * DH, w1q2 + (size_t)l * DMLP * DH,
                sw1 + (size_t)l * DMLP, b1 + (size_t)l * DMLP, z, M, DMLP, DH);
        // quantize z rows
        rowquant_kernel<<<cdiv(NN * 32, 256), 256>>>(z, zq1, zq2, sz, NN, DMLP);
        // h = relu(z @ W2 + b2)    [M,128] fp32
        i8_gemm<128, 128, 64, 32, 3>
            <<<dim3(cdiv(M, 128), 1), 256, SMEM_MAIN>>>(
                zq1, zq2, sz,
                w2q1 + (size_t)l * DH * DMLP, w2q2 + (size_t)l * DH * DMLP,
                sw2 + (size_t)l * DH, b2 + (size_t)l * DH, hnext, M, DH, DMLP);
    }

    // ---- predictor ----
    build_v_quant_kernel<<<cdiv(2 * PP * 32, 256), 256>>>(out_h, psrc, pdst, nsrc, ndst,
                                                          vq1, vq2, sv, PP);
    pred_i8_gemm<<<cdiv(2 * PP, 128), 128, SMEM_PRED>>>(
        vq1, vq2, sv, wpq1, wpq2, swp, bp1, Wp2, bp2, out, 2 * PP, DH);
}

// round 11
// speedup vs baseline: 2.2807x; 2.2807x over previous
#include <cuda_runtime.h>
#include <cuda_bf16.h>
#include <cstdint>

#define NN 100000      // nodes
#define EE 1600000     // edges
#define PP 100000      // pairs (each of pos/neg)
#define DH 128
#define DMLP 512
#define DPRED 64
#define LAYERS 3
#define SCAN_B 1024
#define SCAN_NB ((NN + SCAN_B - 1) / SCAN_B)   // 98

// ---------------- scratch (static device allocations) ----------------
__device__ float g_h[(size_t)NN * DH];                   // fp32 h between layers
__device__ float g_z[(size_t)NN * DMLP];                 // aliased: zh/zl bf16, or Vhi/Vlo
__device__ __nv_bfloat16 g_ah[(size_t)NN * DH];          // agg hi
__device__ __nv_bfloat16 g_al[(size_t)NN * DH];          // agg lo
__device__ __nv_bfloat16 g_w1h[LAYERS * DMLP * DH], g_w1l[LAYERS * DMLP * DH];
__device__ __nv_bfloat16 g_w2h[LAYERS * DH * DMLP], g_w2l[LAYERS * DH * DMLP];
__device__ __nv_bfloat16 g_wp1h[DPRED * DH], g_wp1l[DPRED * DH];
// CSR scratch
__device__ int g_deg[NN];
__device__ int g_incl[NN];
__device__ int g_off[NN];
__device__ int g_cur[NN];
__device__ int g_bsum[128];
__device__ int g_csr[EE];

static inline int cdiv(int a, int b) { return (a + b - 1) / b; }

// ---------------- common helpers ----------------
__device__ __forceinline__ uint32_t swz64(uint32_t off) { return off ^ ((off >> 3) & 0x30u); }

__device__ __forceinline__ void cpasync16(uint32_t dst, const void* src, bool pred) {
    asm volatile("cp.async.cg.shared.global [%0], [%1], 16, %2;"
                 :: "r"(dst), "l"(src), "r"(pred ? 16 : 0) : "memory");
}
__device__ __forceinline__ void cp_commit() {
    asm volatile("cp.async.commit_group;" ::: "memory");
}
template<int N> __device__ __forceinline__ void cp_wait() {
    asm volatile("cp.async.wait_group %0;" :: "n"(N) : "memory");
}

__device__ __forceinline__ void split2(float a, float b, uint32_t& hi, uint32_t& lo) {
    __nv_bfloat16 ha = __float2bfloat16(a), hb = __float2bfloat16(b);
    __nv_bfloat16 la = __float2bfloat16(a - __bfloat162float(ha));
    __nv_bfloat16 lb = __float2bfloat16(b - __bfloat162float(hb));
    __nv_bfloat162 h = __halves2bfloat162(ha, hb), l = __halves2bfloat162(la, lb);
    hi = *reinterpret_cast<uint32_t*>(&h);
    lo = *reinterpret_cast<uint32_t*>(&l);
}

__device__ __forceinline__ void mma_bf16(float* c, const uint32_t* a, const uint32_t* b) {
    asm volatile("mma.sync.aligned.m16n8k16.row.col.f32.bf16.bf16.f32 "
                 "{%0,%1,%2,%3}, {%4,%5,%6,%7}, {%8,%9}, {%0,%1,%2,%3};"
                 : "+f"(c[0]), "+f"(c[1]), "+f"(c[2]), "+f"(c[3])
                 : "r"(a[0]), "r"(a[1]), "r"(a[2]), "r"(a[3]), "r"(b[0]), "r"(b[1]));
}
__device__ __forceinline__ void ldsm4(uint32_t addr, uint32_t* r) {
    asm volatile("ldmatrix.sync.aligned.m8n8.x4.shared.b16 {%0,%1,%2,%3}, [%4];"
                 : "=r"(r[0]), "=r"(r[1]), "=r"(r[2]), "=r"(r[3]) : "r"(addr));
}

// ---------------- CSR build kernels ----------------
__global__ void zero_int_kernel(int* __restrict__ p, int n) {
    int i = blockIdx.x * blockDim.x + threadIdx.x;
    if (i < n) p[i] = 0;
}
__global__ void hist_kernel(const int* __restrict__ dst, int* __restrict__ deg, int E) {
    int e = blockIdx.x * blockDim.x + threadIdx.x;
    if (e < E) atomicAdd(&deg[__ldg(dst + e)], 1);
}
__global__ void scan_block_kernel(const int* __restrict__ deg, int* __restrict__ incl,
                                  int* __restrict__ bsum, int n) {
    __shared__ int sm[SCAN_B];
    int i = blockIdx.x * SCAN_B + threadIdx.x;
    int v = (i < n) ? deg[i] : 0;
    sm[threadIdx.x] = v;
    __syncthreads();
    for (int o = 1; o < SCAN_B; o <<= 1) {
        int t = (threadIdx.x >= o) ? sm[threadIdx.x - o] : 0;
        __syncthreads();
        sm[threadIdx.x] += t;
        __syncthreads();
    }
    if (i < n) incl[i] = sm[threadIdx.x];
    if (threadIdx.x == SCAN_B - 1) bsum[blockIdx.x] = sm[SCAN_B - 1];
}
__global__ void scan_sums_kernel(int* __restrict__ bsum, int nb) {
    __shared__ int sm[128];
    int v = (threadIdx.x < nb) ? bsum[threadIdx.x] : 0;
    sm[threadIdx.x] = v;
    __syncthreads();
    for (int o = 1; o < 128; o <<= 1) {
        int t = (threadIdx.x >= o) ? sm[threadIdx.x - o] : 0;
        __syncthreads();
        sm[threadIdx.x] += t;
        __syncthreads();
    }
    if (threadIdx.x < nb) bsum[threadIdx.x] = sm[threadIdx.x] - v;   // exclusive
}
__global__ void finalize_off_kernel(const int* __restrict__ incl, const int* __restrict__ deg,
                                    const int* __restrict__ bsum,
                                    int* __restrict__ off, int* __restrict__ cur, int n) {
    int i = blockIdx.x * blockDim.x + threadIdx.x;
    if (i >= n) return;
    int o = incl[i] - deg[i] + bsum[i / SCAN_B];
    off[i] = o;
    cur[i] = o;
}
__global__ void fill_kernel(const int* __restrict__ src, const int* __restrict__ dst,
                            int* __restrict__ cur, int* __restrict__ csr, int E) {
    int e = blockIdx.x * blockDim.x + threadIdx.x;
    if (e >= E) return;
    int p = atomicAdd(&cur[__ldg(dst + e)], 1);
    csr[p] = __ldg(src + e);
}

// ---------------- gather + self + bf16 split (warp per node) ----------------
__global__ void gather_split_kernel(const float* __restrict__ h,
                                    const int* __restrict__ off, const int* __restrict__ deg,
                                    const int* __restrict__ csr,
                                    __nv_bfloat16* __restrict__ ah,
                                    __nv_bfloat16* __restrict__ al, int n) {
    int widx = (blockIdx.x * blockDim.x + threadIdx.x) >> 5;
    if (widx >= n) return;
    int c = (threadIdx.x & 31) << 2;
    float4 acc = *(const float4*)(h + (size_t)widx * DH + c);
    int s = __ldg(off + widx);
    int e = s + __ldg(deg + widx);
    int j = s;
    for (; j + 4 <= e; j += 4) {
        int i0 = __ldg(csr + j), i1 = __ldg(csr + j + 1);
        int i2 = __ldg(csr + j + 2), i3 = __ldg(csr + j + 3);
        float4 v0 = *(const float4*)(h + (size_t)i0 * DH + c);
        float4 v1 = *(const float4*)(h + (size_t)i1 * DH + c);
        float4 v2 = *(const float4*)(h + (size_t)i2 * DH + c);
        float4 v3 = *(const float4*)(h + (size_t)i3 * DH + c);
        acc.x += v0.x + v1.x + v2.x + v3.x;
        acc.y += v0.y + v1.y + v2.y + v3.y;
        acc.z += v0.z + v1.z + v2.z + v3.z;
        acc.w += v0.w + v1.w + v2.w + v3.w;
    }
    for (; j < e; j++) {
        int i0 = __ldg(csr + j);
        float4 v0 = *(const float4*)(h + (size_t)i0 * DH + c);
        acc.x += v0.x; acc.y += v0.y; acc.z += v0.z; acc.w += v0.w;
    }
    uint32_t h0, h1, l0, l1;
    split2(acc.x, acc.y, h0, l0);
    split2(acc.z, acc.w, h1, l1);
    size_t o = (size_t)widx * DH + c;
    *(uint2*)(ah + o) = make_uint2(h0, h1);
    *(uint2*)(al + o) = make_uint2(l0, l1);
}

// in[b][R][C] fp32 -> outh/outl [b][C][R] bf16 (transpose + split); R,C multiples of 32
__global__ void transpose_split_kernel(const float* __restrict__ in,
                                       __nv_bfloat16* __restrict__ outh,
                                       __nv_bfloat16* __restrict__ outl, int R, int C) {
    __shared__ float tile[32][33];
    const float* ib = in + (size_t)blockIdx.z * R * C;
    int r = blockIdx.y * 32 + threadIdx.y;
    int c = blockIdx.x * 32 + threadIdx.x;
    tile[threadIdx.y][threadIdx.x] = ib[(size_t)r * C + c];
    __syncthreads();
    int ro = blockIdx.x * 32 + threadIdx.y;
    int co = blockIdx.y * 32 + threadIdx.x;
    float v = tile[threadIdx.x][threadIdx.y];
    __nv_bfloat16 h = __float2bfloat16(v);
    __nv_bfloat16 l = __float2bfloat16(v - __bfloat162float(h));
    size_t o = (size_t)blockIdx.z * R * C + (size_t)ro * R + co;
    outh[o] = h;
    outl[o] = l;
}

// ---------------- split-bf16 tensor-core GEMM, cp.async double-buffered ----------------
// C = relu(A @ B + bias); A as Ahi/Alo [M,K] bf16, B as Bhi/Blo [N,K] bf16 (transposed).
// Warp tile 64x64 (MF=4, NF=8), 128 threads, STAGES=2 (64KB smem -> 2 CTAs/SM).
// One __syncthreads per mainloop iteration (top sync orders arrival AND stage reuse).
// If SPLIT_OUT, writes Chi/Clo bf16; else writes C fp32. N%BN==0, K%32==0, M guarded.
template<int BM, int BN, int WM, int WN, int STAGES, bool SPLIT_OUT>
__global__ void __launch_bounds__((BM / WM) * (BN / WN) * 32, 1)
bf3_gemm(const __nv_bfloat16* __restrict__ Ahi, const __nv_bfloat16* __restrict__ Alo,
         const __nv_bfloat16* __restrict__ Bhi, const __nv_bfloat16* __restrict__ Blo,
         const float* __restrict__ bias,
         float* __restrict__ C, __nv_bfloat16* __restrict__ Chi, __nv_bfloat16* __restrict__ Clo,
         int M, int N, int K) {
    constexpr int THREADS = (BM / WM) * (BN / WN) * 32;
    constexpr int BK = 32;
    constexpr int ATB = BM * BK * 2;
    constexpr int BTB = BN * BK * 2;
    constexpr int STAGE = 2 * ATB + 2 * BTB;
    constexpr int AG = BM * 4;
    constexpr int BG = BN * 4;
    constexpr int MF = WM / 16;
    constexpr int NF = WN / 8;

    extern __shared__ char smem[];
    const uint32_t sbase = (uint32_t)__cvta_generic_to_shared(smem);

    const int tid = threadIdx.x;
    const int lane = tid & 31;
    const int w = tid >> 5;
    constexpr int WN_CNT = BN / WN;
    const int wn = w % WN_CNT;
    const int wm = w / WN_CNT;
    const int row0 = blockIdx.x * BM;
    const int col0 = blockIdx.y * BN;
    const int T = K / BK;

    float acc[MF][NF][4];
#pragma unroll
    for (int i = 0; i < MF; i++)
#pragma unroll
        for (int j = 0; j < NF; j++)
#pragma unroll
            for (int q = 0; q < 4; q++) acc[i][j][q] = 0.f;

    auto load_stage = [&](int s, int t) {
        const uint32_t st = sbase + s * STAGE;
        const int k0 = t * BK;
#pragma unroll
        for (int gid = tid; gid < AG; gid += THREADS) {
            int r = gid >> 2, g = gid & 3;
            bool p = (row0 + r) < M;
            size_t off = (size_t)(row0 + r) * K + k0 + g * 8;
            uint32_t d = st + swz64((uint32_t)(r * 64 + g * 16));
            cpasync16(d, Ahi + off, p);
            cpasync16(d + ATB, Alo + off, p);
        }
#pragma unroll
        for (int gid = tid; gid < BG; gid += THREADS) {
            int r = gid >> 2, g = gid & 3;
            size_t off = (size_t)(col0 + r) * K + k0 + g * 8;
            uint32_t d = st + 2 * ATB + swz64((uint32_t)(r * 64 + g * 16));
            cpasync16(d, Bhi + off, true);
            cpasync16(d + BTB, Blo + off, true);
        }
    };

#pragma unroll
    for (int s = 0; s < STAGES - 1; s++) {
        if (s < T) load_stage(s, s);
        cp_commit();
    }

    const int lrow = lane & 15;
    const int lcolb = ((lane >> 4) & 1) * 16;

    for (int t = 0; t < T; ++t) {
        cp_wait<STAGES - 2>();
        __syncthreads();   // data for stage t arrived; all warps done computing stage t-1
        if (t + STAGES - 1 < T) load_stage((t + STAGES - 1) % STAGES, t + STAGES - 1);
        cp_commit();

        const uint32_t st = sbase + (t % STAGES) * STAGE;
        const uint32_t bAhi = st, bAlo = st + ATB;
        const uint32_t bBhi = st + 2 * ATB, bBlo = bBhi + BTB;
#pragma unroll
        for (int ks = 0; ks < 2; ks++) {
            uint32_t ahi[MF][4], alo[MF][4];
            uint32_t bhi[NF][2], blo[NF][2];
#pragma unroll
            for (int mf = 0; mf < MF; mf++) {
                uint32_t off = swz64((uint32_t)(wm * WM + mf * 16 + lrow) * 64
                                     + ks * 32 + lcolb);
                ldsm4(bAhi + off, ahi[mf]);
                ldsm4(bAlo + off, alo[mf]);
            }
#pragma unroll
            for (int nf2 = 0; nf2 < NF / 2; nf2++) {
                uint32_t off = swz64((uint32_t)(wn * WN + nf2 * 16 + lrow) * 64
                                     + ks * 32 + lcolb);
                uint32_t r4[4];
                ldsm4(bBhi + off, r4);
                bhi[nf2 * 2 + 0][0] = r4[0]; bhi[nf2 * 2 + 1][0] = r4[1];
                bhi[nf2 * 2 + 0][1] = r4[2]; bhi[nf2 * 2 + 1][1] = r4[3];
                ldsm4(bBlo + off, r4);
                blo[nf2 * 2 + 0][0] = r4[0]; blo[nf2 * 2 + 1][0] = r4[1];
                blo[nf2 * 2 + 0][1] = r4[2]; blo[nf2 * 2 + 1][1] = r4[3];
            }
#pragma unroll
            for (int mf = 0; mf < MF; mf++)
#pragma unroll
                for (int nf = 0; nf < NF; nf++) {
                    mma_bf16(acc[mf][nf], ahi[mf], bhi[nf]);
                    mma_bf16(acc[mf][nf], ahi[mf], blo[nf]);
                    mma_bf16(acc[mf][nf], alo[mf], bhi[nf]);
                }
        }
    }

#pragma unroll
    for (int mf = 0; mf < MF; mf++) {
#pragma unroll
        for (int nf = 0; nf < NF; nf++) {
            int r = row0 + wm * WM + mf * 16 + (lane >> 2);
            int c = col0 + wn * WN + nf * 8 + (lane & 3) * 2;
            float b0 = __ldg(bias + c), b1 = __ldg(bias + c + 1);
#pragma unroll
            for (int half = 0; half < 2; half++) {
                int rr = r + half * 8;
                if (rr >= M) continue;
                float v0 = fmaxf(acc[mf][nf][half * 2 + 0] + b0, 0.f);
                float v1 = fmaxf(acc[mf][nf][half * 2 + 1] + b1, 0.f);
                size_t o = (size_t)rr * N + c;
                if (SPLIT_OUT) {
                    uint32_t hi, lo;
                    split2(v0, v1, hi, lo);
                    *(uint32_t*)(Chi + o) = hi;
                    *(uint32_t*)(Clo + o) = lo;
                } else {
                    *(float2*)(C + o) = make_float2(v0, v1);
                }
            }
        }
    }
}

// ================ predictor GEMM with fused matvec epilogue (round-9 proven) ================
// out[r] = relu(V[r,:]@Wp1 + bp1) @ Wp2 + bp2, V split hi/lo. BM=128, BN=N=64, K=128.
__global__ void __launch_bounds__(128)
pred_gemm(const __nv_bfloat16* __restrict__ Ahi, const __nv_bfloat16* __restrict__ Alo,
          const __nv_bfloat16* __restrict__ Bhi, const __nv_bfloat16* __restrict__ Blo,
          const float* __restrict__ bp1, const float* __restrict__ Wp2,
          const float* __restrict__ bp2, float* __restrict__ out,
          int M, int K) {
    constexpr int BM = 128, BN = 64, WM = 64, WN = 32, STAGES = 3, BK = 32;
    constexpr int THREADS = 128;
    constexpr int ATB = BM * BK * 2;
    constexpr int BTB = BN * BK * 2;
    constexpr int STAGE = 2 * ATB + 2 * BTB;
    constexpr int AG = BM * 4;
    constexpr int BG = BN * 4;
    constexpr int MF = WM / 16;   // 4
    constexpr int NF = WN / 8;    // 4

    extern __shared__ char smem[];
    const uint32_t sbase = (uint32_t)__cvta_generic_to_shared(smem);
    float* sred = (float*)smem;

    const int tid = threadIdx.x;
    const int lane = tid & 31;
    const int w = tid >> 5;
    const int wn = w & 1;
    const int wm = w >> 1;
    const int row0 = blockIdx.x * BM;
    const int T = K / BK;

    const int lrow = lane & 15;
    const int lcolb = ((lane >> 4) & 1) * 16;

    float acc[MF][NF][4];
#pragma unroll
    for (int i = 0; i < MF; i++)
#pragma unroll
        for (int j = 0; j < NF; j++)
#pragma unroll
            for (int q = 0; q < 4; q++) acc[i][j][q] = 0.f;

    auto load_stage = [&](int s, int t) {
        const uint32_t st = sbase + s * STAGE;
        const int k0 = t * BK;
#pragma unroll
        for (int gid = tid; gid < AG; gid += THREADS) {
            int r = gid >> 2, g = gid & 3;
            bool p = (row0 + r) < M;
            size_t off = (size_t)(row0 + r) * K + k0 + g * 8;
            uint32_t d = st + swz64((uint32_t)(r * 64 + g * 16));
            cpasync16(d, Ahi + off, p);
            cpasync16(d + ATB, Alo + off, p);
        }
#pragma unroll
        for (int gid = tid; gid < BG; gid += THREADS) {
            int r = gid >> 2, g = gid & 3;
            size_t off = (size_t)r * K + k0 + g * 8;
            uint32_t d = st + 2 * ATB + swz64((uint32_t)(r * 64 + g * 16));
            cpasync16(d, Bhi + off, true);
            cpasync16(d + BTB, Blo + off, true);
        }
    };

#pragma unroll
    for (int s = 0; s < STAGES - 1; s++) {
        if (s < T) load_stage(s, s);
        cp_commit();
    }

    for (int t = 0; t < T; ++t) {
        cp_wait<STAGES - 2>();
        __syncthreads();
        if (t + STAGES - 1 < T) load_stage((t + STAGES - 1) % STAGES, t + STAGES - 1);
        cp_commit();

        const uint32_t st = sbase + (t % STAGES) * STAGE;
        const uint32_t bAhi = st, bAlo = st + ATB;
        const uint32_t bBhi = st + 2 * ATB, bBlo = bBhi + BTB;
#pragma unroll
        for (int ks = 0; ks < 2; ks++) {
            uint32_t ahi[MF][4], alo[MF][4];
            uint32_t bhi[NF][2], blo[NF][2];
#pragma unroll
            for (int mf = 0; mf < MF; mf++) {
                uint32_t off = swz64((uint32_t)(wm * WM + mf * 16 + lrow) * 64
                                     + ks * 32 + lcolb);
                ldsm4(bAhi + off, ahi[mf]);
                ldsm4(bAlo + off, alo[mf]);
            }
#pragma unroll
            for (int nf2 = 0; nf2 < NF / 2; nf2++) {
                uint32_t off = swz64((uint32_t)(wn * WN + nf2 * 16 + lrow) * 64
                                     + ks * 32 + lcolb);
                uint32_t r4[4];
                ldsm4(bBhi + off, r4);
                bhi[nf2 * 2 + 0][0] = r4[0]; bhi[nf2 * 2 + 1][0] = r4[1];
                bhi[nf2 * 2 + 0][1] = r4[2]; bhi[nf2 * 2 + 1][1] = r4[3];
                ldsm4(bBlo + off, r4);
                blo[nf2 * 2 + 0][0] = r4[0]; blo[nf2 * 2 + 1][0] = r4[1];
                blo[nf2 * 2 + 0][1] = r4[2]; blo[nf2 * 2 + 1][1] = r4[3];
            }
#pragma unroll
            for (int mf = 0; mf < MF; mf++)
#pragma unroll
                for (int nf = 0; nf < NF; nf++) {
                    mma_bf16(acc[mf][nf], ahi[mf], bhi[nf]);
                    mma_bf16(acc[mf][nf], ahi[mf], blo[nf]);
                    mma_bf16(acc[mf][nf], alo[mf], bhi[nf]);
                }
        }
        __syncthreads();
    }

    // ---- fused epilogue: zp = relu(acc + bp1); out = zp . Wp2 + bp2 ----
#pragma unroll
    for (int mf = 0; mf < MF; mf++) {
        float part0 = 0.f, part1 = 0.f;
#pragma unroll
        for (int nf = 0; nf < NF; nf++) {
            int c = wn * WN + nf * 8 + (lane & 3) * 2;
            float b0 = __ldg(bp1 + c), b1 = __ldg(bp1 + c + 1);
            float w0 = __ldg(Wp2 + c), w1 = __ldg(Wp2 + c + 1);
            part0 += fmaxf(acc[mf][nf][0] + b0, 0.f) * w0
                   + fmaxf(acc[mf][nf][1] + b1, 0.f) * w1;
            part1 += fmaxf(acc[mf][nf][2] + b0, 0.f) * w0
                   + fmaxf(acc[mf][nf][3] + b1, 0.f) * w1;
        }
#pragma unroll
        for (int o = 1; o < 4; o <<= 1) {
            part0 += __shfl_xor_sync(0xffffffffu, part0, o);
            part1 += __shfl_xor_sync(0xffffffffu, part1, o);
        }
        if ((lane & 3) == 0) {
            int lr = wm * WM + mf * 16 + (lane >> 2);
            sred[wn * 128 + lr] = part0;
            sred[wn * 128 + lr + 8] = part1;
        }
    }
    __syncthreads();
    {
        int r = row0 + tid;
        if (r < M) out[r] = sred[tid] + sred[128 + tid] + __ldg(bp2);
    }
}

// ---------------- predictor: build V rows = h[src]*h[dst], split to bf16 ----------------
__global__ void build_v_kernel(const float* __restrict__ h,
                               const int* __restrict__ psrc, const int* __restrict__ pdst,
                               const int* __restrict__ nsrc, const int* __restrict__ ndst,
                               __nv_bfloat16* __restrict__ Vh,
                               __nv_bfloat16* __restrict__ Vl, int P) {
    int idx = blockIdx.x * blockDim.x + threadIdx.x;
    int p = idx >> 5;
    if (p >= 2 * P) return;
    int c = (idx & 31) << 2;
    int s, d;
    if (p < P) { s = __ldg(psrc + p); d = __ldg(pdst + p); }
    else       { s = __ldg(nsrc + p - P); d = __ldg(ndst + p - P); }
    float4 a = *(const float4*)(h + (size_t)s * DH + c);
    float4 b = *(const float4*)(h + (size_t)d * DH + c);
    uint32_t h0, h1, l0, l1;
    split2(a.x * b.x, a.y * b.y, h0, l0);
    split2(a.z * b.z, a.w * b.w, h1, l1);
    size_t o = (size_t)p * DH + c;
    *(uint2*)(Vh + o) = make_uint2(h0, h1);
    *(uint2*)(Vl + o) = make_uint2(l0, l1);
}

// ---------------- launch ----------------
extern "C" void kernel_launch(void* const* d_in, const int* in_sizes, int n_in,
                              void* d_out, int out_size) {
    const float* x    = (const float*)d_in[0];
    const float* W1   = (const float*)d_in[1];
    const float* b1   = (const float*)d_in[2];
    const float* W2   = (const float*)d_in[3];
    const float* b2   = (const float*)d_in[4];
    const float* Wp1  = (const float*)d_in[5];
    const float* bp1  = (const float*)d_in[6];
    const float* Wp2  = (const float*)d_in[7];
    const float* bp2  = (const float*)d_in[8];
    const int*   esrc = (const int*)d_in[9];
    const int*   edst = (const int*)d_in[10];
    const int*   psrc = (const int*)d_in[11];
    const int*   pdst = (const int*)d_in[12];
    const int*   nsrc = (const int*)d_in[13];
    const int*   ndst = (const int*)d_in[14];
    float* out = (float*)d_out;

    float *hbuf, *z;
    __nv_bfloat16 *ah, *al, *w1h, *w1l, *w2h, *w2l, *wp1h, *wp1l;
    int *deg, *incl, *off, *cur, *bsum, *csr;
    cudaGetSymbolAddress((void**)&hbuf, g_h);
    cudaGetSymbolAddress((void**)&z,    g_z);
    cudaGetSymbolAddress((void**)&ah,   g_ah);
    cudaGetSymbolAddress((void**)&al,   g_al);
    cudaGetSymbolAddress((void**)&w1h,  g_w1h);
    cudaGetSymbolAddress((void**)&w1l,  g_w1l);
    cudaGetSymbolAddress((void**)&w2h,  g_w2h);
    cudaGetSymbolAddress((void**)&w2l,  g_w2l);
    cudaGetSymbolAddress((void**)&wp1h, g_wp1h);
    cudaGetSymbolAddress((void**)&wp1l, g_wp1l);
    cudaGetSymbolAddress((void**)&deg,  g_deg);
    cudaGetSymbolAddress((void**)&incl, g_incl);
    cudaGetSymbolAddress((void**)&off,  g_off);
    cudaGetSymbolAddress((void**)&cur,  g_cur);
    cudaGetSymbolAddress((void**)&bsum, g_bsum);
    cudaGetSymbolAddress((void**)&csr,  g_csr);

    __nv_bfloat16* zh = (__nv_bfloat16*)z;
    __nv_bfloat16* zl = zh + (size_t)NN * DMLP;
    __nv_bfloat16* vh = (__nv_bfloat16*)z;
    __nv_bfloat16* vl = vh + (size_t)2 * PP * DH;

    constexpr int SMEM_MAIN = 2 * 2 * (128 + 128) * 32 * 2;   // 64 KB (2 stages)
    constexpr int SMEM_PRED = 3 * 2 * (128 + 64) * 32 * 2;    // 72 KB
    cudaFuncSetAttribute(bf3_gemm<128, 128, 64, 64, 2, true>,
                         cudaFuncAttributeMaxDynamicSharedMemorySize, SMEM_MAIN);
    cudaFuncSetAttribute(bf3_gemm<128, 128, 64, 64, 2, false>,
                         cudaFuncAttributeMaxDynamicSharedMemorySize, SMEM_MAIN);
    cudaFuncSetAttribute(pred_gemm,
                         cudaFuncAttributeMaxDynamicSharedMemorySize, SMEM_PRED);

    float* out_h = out + 2 * PP;   // final h ([N,128]) lives in output

    // ---- CSR build (once per launch) ----
    zero_int_kernel<<<cdiv(NN, 256), 256>>>(deg, NN);
    hist_kernel<<<cdiv(EE, 256), 256>>>(edst, deg, EE);
    scan_block_kernel<<<SCAN_NB, SCAN_B>>>(deg, incl, bsum, NN);
    scan_sums_kernel<<<1, 128>>>(bsum, SCAN_NB);
    finalize_off_kernel<<<cdiv(NN, 256), 256>>>(incl, deg, bsum, off, cur, NN);
    fill_kernel<<<cdiv(EE, 256), 256>>>(esrc, edst, cur, csr, EE);

    // ---- weight transpose+split (tiny) ----
    transpose_split_kernel<<<dim3(DMLP / 32, DH / 32, LAYERS), dim3(32, 32)>>>(W1, w1h, w1l, DH, DMLP);
    transpose_split_kernel<<<dim3(DH / 32, DMLP / 32, LAYERS), dim3(32, 32)>>>(W2, w2h, w2l, DMLP, DH);
    transpose_split_kernel<<<dim3(DPRED / 32, DH / 32, 1), dim3(32, 32)>>>(Wp1, wp1h, wp1l, DH, DPRED);

    const int M = NN;
    for (int l = 0; l < LAYERS; l++) {
        const float* hcur = (l == 0) ? x : hbuf;
        float* hnext = (l == LAYERS - 1) ? out_h : hbuf;

        // agg = h[n] + sum_neighbors h[src], split to bf16 hi/lo (one fused kernel)
        gather_split_kernel<<<cdiv(NN * 32, 256), 256>>>(hcur, off, deg, csr, ah, al, NN);
        // z = relu(agg @ W1 + b1)  -> split bf16 out
        bf3_gemm<128, 128, 64, 64, 2, true>
            <<<dim3(cdiv(M, 128), DMLP / 128), 128, SMEM_MAIN>>>(
                ah, al, w1h + (size_t)l * DMLP * DH, w1l + (size_t)l * DMLP * DH,
                b1 + (size_t)l * DMLP, nullptr, zh, zl, M, DMLP, DH);
        // h = relu(z @ W2 + b2)    -> fp32 out
        bf3_gemm<128, 128, 64, 64, 2, false>
            <<<dim3(cdiv(M, 128), 1), 128, SMEM_MAIN>>>(
                zh, zl, w2h + (size_t)l * DH * DMLP, w2l + (size_t)l * DH * DMLP,
                b2 + (size_t)l * DH, hnext, nullptr, nullptr, M, DH, DMLP);
    }

    // ---- predictor: V build, then fused GEMM + matvec epilogue ----
    build_v_kernel<<<cdiv(2 * PP * 32, 256), 256>>>(out_h, psrc, pdst, nsrc, ndst, vh, vl, PP);
    pred_gemm<<<cdiv(2 * PP, 128), 128, SMEM_PRED>>>(
        vh, vl, wp1h, wp1l, bp1, Wp2, bp2, out, 2 * PP, DH);
}

// round 12
// speedup vs baseline: 2.3257x; 1.0197x over previous
#include <cuda_runtime.h>
#include <cuda_bf16.h>
#include <cstdint>

#define NN 100000      // nodes
#define EE 1600000     // edges
#define PP 100000      // pairs (each of pos/neg)
#define DH 128
#define DMLP 512
#define DPRED 64
#define LAYERS 3
#define SCAN_B 1024
#define SCAN_NB ((NN + SCAN_B - 1) / SCAN_B)   // 98

// ---------------- scratch (static device allocations) ----------------
__device__ float g_h[(size_t)NN * DH];                   // fp32 h between layers
__device__ float g_z[(size_t)NN * DMLP];                 // aliased: zh/zl bf16, or Vhi/Vlo
__device__ __nv_bfloat16 g_ah[(size_t)NN * DH];          // agg hi
__device__ __nv_bfloat16 g_al[(size_t)NN * DH];          // agg lo
__device__ __nv_bfloat16 g_w1h[LAYERS * DMLP * DH], g_w1l[LAYERS * DMLP * DH];
__device__ __nv_bfloat16 g_w2h[LAYERS * DH * DMLP], g_w2l[LAYERS * DH * DMLP];
__device__ __nv_bfloat16 g_wp1h[DPRED * DH], g_wp1l[DPRED * DH];
// CSR scratch
__device__ int g_deg[NN];
__device__ int g_incl[NN];
__device__ int g_off[NN];
__device__ int g_cur[NN];
__device__ int g_bsum[128];
__device__ int g_csr[EE];

static inline int cdiv(int a, int b) { return (a + b - 1) / b; }

// ---------------- common helpers ----------------
__device__ __forceinline__ uint32_t swz64(uint32_t off) { return off ^ ((off >> 3) & 0x30u); }

__device__ __forceinline__ void cpasync16(uint32_t dst, const void* src, bool pred) {
    asm volatile("cp.async.cg.shared.global [%0], [%1], 16, %2;"
                 :: "r"(dst), "l"(src), "r"(pred ? 16 : 0) : "memory");
}
__device__ __forceinline__ void cp_commit() {
    asm volatile("cp.async.commit_group;" ::: "memory");
}
template<int N> __device__ __forceinline__ void cp_wait() {
    asm volatile("cp.async.wait_group %0;" :: "n"(N) : "memory");
}

__device__ __forceinline__ void split2(float a, float b, uint32_t& hi, uint32_t& lo) {
    __nv_bfloat16 ha = __float2bfloat16(a), hb = __float2bfloat16(b);
    __nv_bfloat16 la = __float2bfloat16(a - __bfloat162float(ha));
    __nv_bfloat16 lb = __float2bfloat16(b - __bfloat162float(hb));
    __nv_bfloat162 h = __halves2bfloat162(ha, hb), l = __halves2bfloat162(la, lb);
    hi = *reinterpret_cast<uint32_t*>(&h);
    lo = *reinterpret_cast<uint32_t*>(&l);
}

__device__ __forceinline__ void mma_bf16(float* c, const uint32_t* a, const uint32_t* b) {
    asm volatile("mma.sync.aligned.m16n8k16.row.col.f32.bf16.bf16.f32 "
                 "{%0,%1,%2,%3}, {%4,%5,%6,%7}, {%8,%9}, {%0,%1,%2,%3};"
                 : "+f"(c[0]), "+f"(c[1]), "+f"(c[2]), "+f"(c[3])
                 : "r"(a[0]), "r"(a[1]), "r"(a[2]), "r"(a[3]), "r"(b[0]), "r"(b[1]));
}
__device__ __forceinline__ void ldsm4(uint32_t addr, uint32_t* r) {
    asm volatile("ldmatrix.sync.aligned.m8n8.x4.shared.b16 {%0,%1,%2,%3}, [%4];"
                 : "=r"(r[0]), "=r"(r[1]), "=r"(r[2]), "=r"(r[3]) : "r"(addr));
}

// ---------------- CSR build kernels ----------------
__global__ void zero_int_kernel(int* __restrict__ p, int n) {
    int i = blockIdx.x * blockDim.x + threadIdx.x;
    if (i < n) p[i] = 0;
}
__global__ void hist_kernel(const int* __restrict__ dst, int* __restrict__ deg, int E) {
    int e = blockIdx.x * blockDim.x + threadIdx.x;
    if (e < E) atomicAdd(&deg[__ldg(dst + e)], 1);
}
__global__ void scan_block_kernel(const int* __restrict__ deg, int* __restrict__ incl,
                                  int* __restrict__ bsum, int n) {
    __shared__ int sm[SCAN_B];
    int i = blockIdx.x * SCAN_B + threadIdx.x;
    int v = (i < n) ? deg[i] : 0;
    sm[threadIdx.x] = v;
    __syncthreads();
    for (int o = 1; o < SCAN_B; o <<= 1) {
        int t = (threadIdx.x >= o) ? sm[threadIdx.x - o] : 0;
        __syncthreads();
        sm[threadIdx.x] += t;
        __syncthreads();
    }
    if (i < n) incl[i] = sm[threadIdx.x];
    if (threadIdx.x == SCAN_B - 1) bsum[blockIdx.x] = sm[SCAN_B - 1];
}
__global__ void scan_sums_kernel(int* __restrict__ bsum, int nb) {
    __shared__ int sm[128];
    int v = (threadIdx.x < nb) ? bsum[threadIdx.x] : 0;
    sm[threadIdx.x] = v;
    __syncthreads();
    for (int o = 1; o < 128; o <<= 1) {
        int t = (threadIdx.x >= o) ? sm[threadIdx.x - o] : 0;
        __syncthreads();
        sm[threadIdx.x] += t;
        __syncthreads();
    }
    if (threadIdx.x < nb) bsum[threadIdx.x] = sm[threadIdx.x] - v;   // exclusive
}
__global__ void finalize_off_kernel(const int* __restrict__ incl, const int* __restrict__ deg,
                                    const int* __restrict__ bsum,
                                    int* __restrict__ off, int* __restrict__ cur, int n) {
    int i = blockIdx.x * blockDim.x + threadIdx.x;
    if (i >= n) return;
    int o = incl[i] - deg[i] + bsum[i / SCAN_B];
    off[i] = o;
    cur[i] = o;
}
__global__ void fill_kernel(const int* __restrict__ src, const int* __restrict__ dst,
                            int* __restrict__ cur, int* __restrict__ csr, int E) {
    int e = blockIdx.x * blockDim.x + threadIdx.x;
    if (e >= E) return;
    int p = atomicAdd(&cur[__ldg(dst + e)], 1);
    csr[p] = __ldg(src + e);
}

// ---------------- gather + self + bf16 split (warp per node) ----------------
__global__ void gather_split_kernel(const float* __restrict__ h,
                                    const int* __restrict__ off, const int* __restrict__ deg,
                                    const int* __restrict__ csr,
                                    __nv_bfloat16* __restrict__ ah,
                                    __nv_bfloat16* __restrict__ al, int n) {
    int widx = (blockIdx.x * blockDim.x + threadIdx.x) >> 5;
    if (widx >= n) return;
    int c = (threadIdx.x & 31) << 2;
    float4 acc = *(const float4*)(h + (size_t)widx * DH + c);
    int s = __ldg(off + widx);
    int e = s + __ldg(deg + widx);
    int j = s;
    for (; j + 4 <= e; j += 4) {
        int i0 = __ldg(csr + j), i1 = __ldg(csr + j + 1);
        int i2 = __ldg(csr + j + 2), i3 = __ldg(csr + j + 3);
        float4 v0 = *(const float4*)(h + (size_t)i0 * DH + c);
        float4 v1 = *(const float4*)(h + (size_t)i1 * DH + c);
        float4 v2 = *(const float4*)(h + (size_t)i2 * DH + c);
        float4 v3 = *(const float4*)(h + (size_t)i3 * DH + c);
        acc.x += v0.x + v1.x + v2.x + v3.x;
        acc.y += v0.y + v1.y + v2.y + v3.y;
        acc.z += v0.z + v1.z + v2.z + v3.z;
        acc.w += v0.w + v1.w + v2.w + v3.w;
    }
    for (; j < e; j++) {
        int i0 = __ldg(csr + j);
        float4 v0 = *(const float4*)(h + (size_t)i0 * DH + c);
        acc.x += v0.x; acc.y += v0.y; acc.z += v0.z; acc.w += v0.w;
    }
    uint32_t h0, h1, l0, l1;
    split2(acc.x, acc.y, h0, l0);
    split2(acc.z, acc.w, h1, l1);
    size_t o = (size_t)widx * DH + c;
    *(uint2*)(ah + o) = make_uint2(h0, h1);
    *(uint2*)(al + o) = make_uint2(l0, l1);
}

// in[b][R][C] fp32 -> outh/outl [b][C][R] bf16 (transpose + split); R,C multiples of 32
__global__ void transpose_split_kernel(const float* __restrict__ in,
                                       __nv_bfloat16* __restrict__ outh,
                                       __nv_bfloat16* __restrict__ outl, int R, int C) {
    __shared__ float tile[32][33];
    const float* ib = in + (size_t)blockIdx.z * R * C;
    int r = blockIdx.y * 32 + threadIdx.y;
    int c = blockIdx.x * 32 + threadIdx.x;
    tile[threadIdx.y][threadIdx.x] = ib[(size_t)r * C + c];
    __syncthreads();
    int ro = blockIdx.x * 32 + threadIdx.y;
    int co = blockIdx.y * 32 + threadIdx.x;
    float v = tile[threadIdx.x][threadIdx.y];
    __nv_bfloat16 h = __float2bfloat16(v);
    __nv_bfloat16 l = __float2bfloat16(v - __bfloat162float(h));
    size_t o = (size_t)blockIdx.z * R * C + (size_t)ro * R + co;
    outh[o] = h;
    outl[o] = l;
}

// ---------------- split-bf16 tensor-core GEMM, cp.async multistage (round-9 config) ----------------
// Single __syncthreads per mainloop iteration: the top sync (after cp_wait) both
// publishes the arrived stage and guarantees all warps finished computing the
// stage about to be overwritten (it was computed at iteration t-1, before this barrier).
template<int BM, int BN, int WM, int WN, int STAGES, bool SPLIT_OUT>
__global__ void __launch_bounds__((BM / WM) * (BN / WN) * 32)
bf3_gemm(const __nv_bfloat16* __restrict__ Ahi, const __nv_bfloat16* __restrict__ Alo,
         const __nv_bfloat16* __restrict__ Bhi, const __nv_bfloat16* __restrict__ Blo,
         const float* __restrict__ bias,
         float* __restrict__ C, __nv_bfloat16* __restrict__ Chi, __nv_bfloat16* __restrict__ Clo,
         int M, int N, int K) {
    constexpr int THREADS = (BM / WM) * (BN / WN) * 32;
    constexpr int BK = 32;
    constexpr int ATB = BM * BK * 2;
    constexpr int BTB = BN * BK * 2;
    constexpr int STAGE = 2 * ATB + 2 * BTB;
    constexpr int AG = BM * 4;
    constexpr int BG = BN * 4;
    constexpr int MF = WM / 16;
    constexpr int NF = WN / 8;

    extern __shared__ char smem[];
    const uint32_t sbase = (uint32_t)__cvta_generic_to_shared(smem);

    const int tid = threadIdx.x;
    const int lane = tid & 31;
    const int w = tid >> 5;
    constexpr int WN_CNT = BN / WN;
    const int wn = w % WN_CNT;
    const int wm = w / WN_CNT;
    const int row0 = blockIdx.x * BM;
    const int col0 = blockIdx.y * BN;
    const int T = K / BK;

    float acc[MF][NF][4];
#pragma unroll
    for (int i = 0; i < MF; i++)
#pragma unroll
        for (int j = 0; j < NF; j++)
#pragma unroll
            for (int q = 0; q < 4; q++) acc[i][j][q] = 0.f;

    auto load_stage = [&](int s, int t) {
        const uint32_t st = sbase + s * STAGE;
        const int k0 = t * BK;
#pragma unroll
        for (int gid = tid; gid < AG; gid += THREADS) {
            int r = gid >> 2, g = gid & 3;
            bool p = (row0 + r) < M;
            size_t off = (size_t)(row0 + r) * K + k0 + g * 8;
            uint32_t d = st + swz64((uint32_t)(r * 64 + g * 16));
            cpasync16(d, Ahi + off, p);
            cpasync16(d + ATB, Alo + off, p);
        }
#pragma unroll
        for (int gid = tid; gid < BG; gid += THREADS) {
            int r = gid >> 2, g = gid & 3;
            size_t off = (size_t)(col0 + r) * K + k0 + g * 8;
            uint32_t d = st + 2 * ATB + swz64((uint32_t)(r * 64 + g * 16));
            cpasync16(d, Bhi + off, true);
            cpasync16(d + BTB, Blo + off, true);
        }
    };

#pragma unroll
    for (int s = 0; s < STAGES - 1; s++) {
        if (s < T) load_stage(s, s);
        cp_commit();
    }

    const int lrow = lane & 15;
    const int lcolb = ((lane >> 4) & 1) * 16;

    for (int t = 0; t < T; ++t) {
        cp_wait<STAGES - 2>();
        __syncthreads();   // publishes stage t AND all warps done with the stage we reload below
        if (t + STAGES - 1 < T) load_stage((t + STAGES - 1) % STAGES, t + STAGES - 1);
        cp_commit();

        const uint32_t st = sbase + (t % STAGES) * STAGE;
        const uint32_t bAhi = st, bAlo = st + ATB;
        const uint32_t bBhi = st + 2 * ATB, bBlo = bBhi + BTB;
#pragma unroll
        for (int ks = 0; ks < 2; ks++) {
            uint32_t ahi[MF][4], alo[MF][4];
            uint32_t bhi[NF][2], blo[NF][2];
#pragma unroll
            for (int mf = 0; mf < MF; mf++) {
                uint32_t off = swz64((uint32_t)(wm * WM + mf * 16 + lrow) * 64
                                     + ks * 32 + lcolb);
                ldsm4(bAhi + off, ahi[mf]);
                ldsm4(bAlo + off, alo[mf]);
            }
#pragma unroll
            for (int nf2 = 0; nf2 < NF / 2; nf2++) {
                uint32_t off = swz64((uint32_t)(wn * WN + nf2 * 16 + lrow) * 64
                                     + ks * 32 + lcolb);
                uint32_t r4[4];
                ldsm4(bBhi + off, r4);
                bhi[nf2 * 2 + 0][0] = r4[0]; bhi[nf2 * 2 + 1][0] = r4[1];
                bhi[nf2 * 2 + 0][1] = r4[2]; bhi[nf2 * 2 + 1][1] = r4[3];
                ldsm4(bBlo + off, r4);
                blo[nf2 * 2 + 0][0] = r4[0]; blo[nf2 * 2 + 1][0] = r4[1];
                blo[nf2 * 2 + 0][1] = r4[2]; blo[nf2 * 2 + 1][1] = r4[3];
            }
#pragma unroll
            for (int mf = 0; mf < MF; mf++)
#pragma unroll
                for (int nf = 0; nf < NF; nf++) {
                    mma_bf16(acc[mf][nf], ahi[mf], bhi[nf]);
                    mma_bf16(acc[mf][nf], ahi[mf], blo[nf]);
                    mma_bf16(acc[mf][nf], alo[mf], bhi[nf]);
                }
        }
    }

#pragma unroll
    for (int mf = 0; mf < MF; mf++) {
#pragma unroll
        for (int nf = 0; nf < NF; nf++) {
            int r = row0 + wm * WM + mf * 16 + (lane >> 2);
            int c = col0 + wn * WN + nf * 8 + (lane & 3) * 2;
            float b0 = __ldg(bias + c), b1 = __ldg(bias + c + 1);
#pragma unroll
            for (int half = 0; half < 2; half++) {
                int rr = r + half * 8;
                if (rr >= M) continue;
                float v0 = fmaxf(acc[mf][nf][half * 2 + 0] + b0, 0.f);
                float v1 = fmaxf(acc[mf][nf][half * 2 + 1] + b1, 0.f);
                size_t o = (size_t)rr * N + c;
                if (SPLIT_OUT) {
                    uint32_t hi, lo;
                    split2(v0, v1, hi, lo);
                    *(uint32_t*)(Chi + o) = hi;
                    *(uint32_t*)(Clo + o) = lo;
                } else {
                    *(float2*)(C + o) = make_float2(v0, v1);
                }
            }
        }
    }
}

// ================ predictor GEMM with fused matvec epilogue ================
__global__ void __launch_bounds__(128)
pred_gemm(const __nv_bfloat16* __restrict__ Ahi, const __nv_bfloat16* __restrict__ Alo,
          const __nv_bfloat16* __restrict__ Bhi, const __nv_bfloat16* __restrict__ Blo,
          const float* __restrict__ bp1, const float* __restrict__ Wp2,
          const float* __restrict__ bp2, float* __restrict__ out,
          int M, int K) {
    constexpr int BM = 128, BN = 64, WM = 64, WN = 32, STAGES = 3, BK = 32;
    constexpr int THREADS = 128;
    constexpr int ATB = BM * BK * 2;
    constexpr int BTB = BN * BK * 2;
    constexpr int STAGE = 2 * ATB + 2 * BTB;
    constexpr int AG = BM * 4;
    constexpr int BG = BN * 4;
    constexpr int MF = WM / 16;
    constexpr int NF = WN / 8;

    extern __shared__ char smem[];
    const uint32_t sbase = (uint32_t)__cvta_generic_to_shared(smem);
    float* sred = (float*)smem;

    const int tid = threadIdx.x;
    const int lane = tid & 31;
    const int w = tid >> 5;
    const int wn = w & 1;
    const int wm = w >> 1;
    const int row0 = blockIdx.x * BM;
    const int T = K / BK;

    const int lrow = lane & 15;
    const int lcolb = ((lane >> 4) & 1) * 16;

    float acc[MF][NF][4];
#pragma unroll
    for (int i = 0; i < MF; i++)
#pragma unroll
        for (int j = 0; j < NF; j++)
#pragma unroll
            for (int q = 0; q < 4; q++) acc[i][j][q] = 0.f;

    auto load_stage = [&](int s, int t) {
        const uint32_t st = sbase + s * STAGE;
        const int k0 = t * BK;
#pragma unroll
        for (int gid = tid; gid < AG; gid += THREADS) {
            int r = gid >> 2, g = gid & 3;
            bool p = (row0 + r) < M;
            size_t off = (size_t)(row0 + r) * K + k0 + g * 8;
            uint32_t d = st + swz64((uint32_t)(r * 64 + g * 16));
            cpasync16(d, Ahi + off, p);
            cpasync16(d + ATB, Alo + off, p);
        }
#pragma unroll
        for (int gid = tid; gid < BG; gid += THREADS) {
            int r = gid >> 2, g = gid & 3;
            size_t off = (size_t)r * K + k0 + g * 8;
            uint32_t d = st + 2 * ATB + swz64((uint32_t)(r * 64 + g * 16));
            cpasync16(d, Bhi + off, true);
            cpasync16(d + BTB, Blo + off, true);
        }
    };

#pragma unroll
    for (int s = 0; s < STAGES - 1; s++) {
        if (s < T) load_stage(s, s);
        cp_commit();
    }

    for (int t = 0; t < T; ++t) {
        cp_wait<STAGES - 2>();
        __syncthreads();
        if (t + STAGES - 1 < T) load_stage((t + STAGES - 1) % STAGES, t + STAGES - 1);
        cp_commit();

        const uint32_t st = sbase + (t % STAGES) * STAGE;
        const uint32_t bAhi = st, bAlo = st + ATB;
        const uint32_t bBhi = st + 2 * ATB, bBlo = bBhi + BTB;
#pragma unroll
        for (int ks = 0; ks < 2; ks++) {
            uint32_t ahi[MF][4], alo[MF][4];
            uint32_t bhi[NF][2], blo[NF][2];
#pragma unroll
            for (int mf = 0; mf < MF; mf++) {
                uint32_t off = swz64((uint32_t)(wm * WM + mf * 16 + lrow) * 64
                                     + ks * 32 + lcolb);
                ldsm4(bAhi + off, ahi[mf]);
                ldsm4(bAlo + off, alo[mf]);
            }
#pragma unroll
            for (int nf2 = 0; nf2 < NF / 2; nf2++) {
                uint32_t off = swz64((uint32_t)(wn * WN + nf2 * 16 + lrow) * 64
                                     + ks * 32 + lcolb);
                uint32_t r4[4];
                ldsm4(bBhi + off, r4);
                bhi[nf2 * 2 + 0][0] = r4[0]; bhi[nf2 * 2 + 1][0] = r4[1];
                bhi[nf2 * 2 + 0][1] = r4[2]; bhi[nf2 * 2 + 1][1] = r4[3];
                ldsm4(bBlo + off, r4);
                blo[nf2 * 2 + 0][0] = r4[0]; blo[nf2 * 2 + 1][0] = r4[1];
                blo[nf2 * 2 + 0][1] = r4[2]; blo[nf2 * 2 + 1][1] = r4[3];
            }
#pragma unroll
            for (int mf = 0; mf < MF; mf++)
#pragma unroll
                for (int nf = 0; nf < NF; nf++) {
                    mma_bf16(acc[mf][nf], ahi[mf], bhi[nf]);
                    mma_bf16(acc[mf][nf], ahi[mf], blo[nf]);
                    mma_bf16(acc[mf][nf], alo[mf], bhi[nf]);
                }
        }
    }
    __syncthreads();   // all warps done with mainloop smem before sred reuse

    // ---- fused epilogue: zp = relu(acc + bp1); out = zp . Wp2 + bp2 ----
#pragma unroll
    for (int mf = 0; mf < MF; mf++) {
        float part0 = 0.f, part1 = 0.f;
#pragma unroll
        for (int nf = 0; nf < NF; nf++) {
            int c = wn * WN + nf * 8 + (lane & 3) * 2;
            float b0 = __ldg(bp1 + c), b1 = __ldg(bp1 + c + 1);
            float w0 = __ldg(Wp2 + c), w1 = __ldg(Wp2 + c + 1);
            part0 += fmaxf(acc[mf][nf][0] + b0, 0.f) * w0
                   + fmaxf(acc[mf][nf][1] + b1, 0.f) * w1;
            part1 += fmaxf(acc[mf][nf][2] + b0, 0.f) * w0
                   + fmaxf(acc[mf][nf][3] + b1, 0.f) * w1;
        }
#pragma unroll
        for (int o = 1; o < 4; o <<= 1) {
            part0 += __shfl_xor_sync(0xffffffffu, part0, o);
            part1 += __shfl_xor_sync(0xffffffffu, part1, o);
        }
        if ((lane & 3) == 0) {
            int lr = wm * WM + mf * 16 + (lane >> 2);
            sred[wn * 128 + lr] = part0;
            sred[wn * 128 + lr + 8] = part1;
        }
    }
    __syncthreads();
    {
        int r = row0 + tid;
        if (r < M) out[r] = sred[tid] + sred[128 + tid] + __ldg(bp2);
    }
}

// ---------------- predictor: build V rows = h[src]*h[dst], split to bf16 ----------------
__global__ void build_v_kernel(const float* __restrict__ h,
                               const int* __restrict__ psrc, const int* __restrict__ pdst,
                               const int* __restrict__ nsrc, const int* __restrict__ ndst,
                               __nv_bfloat16* __restrict__ Vh,
                               __nv_bfloat16* __restrict__ Vl, int P) {
    int idx = blockIdx.x * blockDim.x + threadIdx.x;
    int p = idx >> 5;
    if (p >= 2 * P) return;
    int c = (idx & 31) << 2;
    int s, d;
    if (p < P) { s = __ldg(psrc + p); d = __ldg(pdst + p); }
    else       { s = __ldg(nsrc + p - P); d = __ldg(ndst + p - P); }
    float4 a = *(const float4*)(h + (size_t)s * DH + c);
    float4 b = *(const float4*)(h + (size_t)d * DH + c);
    uint32_t h0, h1, l0, l1;
    split2(a.x * b.x, a.y * b.y, h0, l0);
    split2(a.z * b.z, a.w * b.w, h1, l1);
    size_t o = (size_t)p * DH + c;
    *(uint2*)(Vh + o) = make_uint2(h0, h1);
    *(uint2*)(Vl + o) = make_uint2(l0, l1);
}

// ---------------- launch ----------------
extern "C" void kernel_launch(void* const* d_in, const int* in_sizes, int n_in,
                              void* d_out, int out_size) {
    const float* x    = (const float*)d_in[0];
    const float* W1   = (const float*)d_in[1];
    const float* b1   = (const float*)d_in[2];
    const float* W2   = (const float*)d_in[3];
    const float* b2   = (const float*)d_in[4];
    const float* Wp1  = (const float*)d_in[5];
    const float* bp1  = (const float*)d_in[6];
    const float* Wp2  = (const float*)d_in[7];
    const float* bp2  = (const float*)d_in[8];
    const int*   esrc = (const int*)d_in[9];
    const int*   edst = (const int*)d_in[10];
    const int*   psrc = (const int*)d_in[11];
    const int*   pdst = (const int*)d_in[12];
    const int*   nsrc = (const int*)d_in[13];
    const int*   ndst = (const int*)d_in[14];
    float* out = (float*)d_out;

    float *hbuf, *z;
    __nv_bfloat16 *ah, *al, *w1h, *w1l, *w2h, *w2l, *wp1h, *wp1l;
    int *deg, *incl, *off, *cur, *bsum, *csr;
    cudaGetSymbolAddress((void**)&hbuf, g_h);
    cudaGetSymbolAddress((void**)&z,    g_z);
    cudaGetSymbolAddress((void**)&ah,   g_ah);
    cudaGetSymbolAddress((void**)&al,   g_al);
    cudaGetSymbolAddress((void**)&w1h,  g_w1h);
    cudaGetSymbolAddress((void**)&w1l,  g_w1l);
    cudaGetSymbolAddress((void**)&w2h,  g_w2h);
    cudaGetSymbolAddress((void**)&w2l,  g_w2l);
    cudaGetSymbolAddress((void**)&wp1h, g_wp1h);
    cudaGetSymbolAddress((void**)&wp1l, g_wp1l);
    cudaGetSymbolAddress((void**)&deg,  g_deg);
    cudaGetSymbolAddress((void**)&incl, g_incl);
    cudaGetSymbolAddress((void**)&off,  g_off);
    cudaGetSymbolAddress((void**)&cur,  g_cur);
    cudaGetSymbolAddress((void**)&bsum, g_bsum);
    cudaGetSymbolAddress((void**)&csr,  g_csr);

    __nv_bfloat16* zh = (__nv_bfloat16*)z;
    __nv_bfloat16* zl = zh + (size_t)NN * DMLP;
    __nv_bfloat16* vh = (__nv_bfloat16*)z;
    __nv_bfloat16* vl = vh + (size_t)2 * PP * DH;

    constexpr int SMEM_MAIN = 3 * 2 * (128 + 128) * 32 * 2;   // 96 KB
    constexpr int SMEM_PRED = 3 * 2 * (128 + 64) * 32 * 2;    // 72 KB
    cudaFuncSetAttribute(bf3_gemm<128, 128, 64, 32, 3, true>,
                         cudaFuncAttributeMaxDynamicSharedMemorySize, SMEM_MAIN);
    cudaFuncSetAttribute(bf3_gemm<128, 128, 64, 32, 3, false>,
                         cudaFuncAttributeMaxDynamicSharedMemorySize, SMEM_MAIN);
    cudaFuncSetAttribute(pred_gemm,
                         cudaFuncAttributeMaxDynamicSharedMemorySize, SMEM_PRED);

    float* out_h = out + 2 * PP;   // final h ([N,128]) lives in output

    // ---- fork: weight transposes on a side stream, CSR build on the main stream ----
    // (streams/events created per call and intentionally not destroyed mid-capture;
    //  kernel_launch is only invoked a handful of times: correctness + capture)
    cudaStream_t s2;
    cudaStreamCreateWithFlags(&s2, cudaStreamNonBlocking);
    cudaEvent_t evFork, evJoin;
    cudaEventCreateWithFlags(&evFork, cudaEventDisableTiming);
    cudaEventCreateWithFlags(&evJoin, cudaEventDisableTiming);

    cudaEventRecord(evFork, 0);
    cudaStreamWaitEvent(s2, evFork, 0);
    transpose_split_kernel<<<dim3(DMLP / 32, DH / 32, LAYERS), dim3(32, 32), 0, s2>>>(
        W1, w1h, w1l, DH, DMLP);
    transpose_split_kernel<<<dim3(DH / 32, DMLP / 32, LAYERS), dim3(32, 32), 0, s2>>>(
        W2, w2h, w2l, DMLP, DH);
    transpose_split_kernel<<<dim3(DPRED / 32, DH / 32, 1), dim3(32, 32), 0, s2>>>(
        Wp1, wp1h, wp1l, DH, DPRED);
    cudaEventRecord(evJoin, s2);

    // ---- CSR build (main stream, parallel with transposes) ----
    zero_int_kernel<<<cdiv(NN, 256), 256>>>(deg, NN);
    hist_kernel<<<cdiv(EE, 256), 256>>>(edst, deg, EE);
    scan_block_kernel<<<SCAN_NB, SCAN_B>>>(deg, incl, bsum, NN);
    scan_sums_kernel<<<1, 128>>>(bsum, SCAN_NB);
    finalize_off_kernel<<<cdiv(NN, 256), 256>>>(incl, deg, bsum, off, cur, NN);
    fill_kernel<<<cdiv(EE, 256), 256>>>(esrc, edst, cur, csr, EE);

    cudaStreamWaitEvent(0, evJoin, 0);   // join before GEMMs consume weights

    const int M = NN;
    for (int l = 0; l < LAYERS; l++) {
        const float* hcur = (l == 0) ? x : hbuf;
        float* hnext = (l == LAYERS - 1) ? out_h : hbuf;

        gather_split_kernel<<<cdiv(NN * 32, 256), 256>>>(hcur, off, deg, csr, ah, al, NN);
        bf3_gemm<128, 128, 64, 32, 3, true>
            <<<dim3(cdiv(M, 128), DMLP / 128), 256, SMEM_MAIN>>>(
                ah, al, w1h + (size_t)l * DMLP * DH, w1l + (size_t)l * DMLP * DH,
                b1 + (size_t)l * DMLP, nullptr, zh, zl, M, DMLP, DH);
        bf3_gemm<128, 128, 64, 32, 3, false>
            <<<dim3(cdiv(M, 128), 1), 256, SMEM_MAIN>>>(
                zh, zl, w2h + (size_t)l * DH * DMLP, w2l + (size_t)l * DH * DMLP,
                b2 + (size_t)l * DH, hnext, nullptr, nullptr, M, DH, DMLP);
    }

    // ---- predictor: V build, then fused GEMM + matvec epilogue ----
    build_v_kernel<<<cdiv(2 * PP * 32, 256), 256>>>(out_h, psrc, pdst, nsrc, ndst, vh, vl, PP);
    pred_gemm<<<cdiv(2 * PP, 128), 128, SMEM_PRED>>>(
        vh, vl, wp1h, wp1l, bp1, Wp2, bp2, out, 2 * PP, DH);
}